// round 1
// baseline (speedup 1.0000x reference)
#include <cuda_runtime.h>
#include <math.h>

#define L   256
#define DP  128
#define DB  128
#define H   8
#define DH  32
#define HD  256      // H*DH
#define LL  (L*L)    // 65536
#define LDH (L*DH)   // 8192

// ---------------- scratch (device globals; no runtime alloc) ----------------
__device__ float g_Pn[LL*DP];     // LN'd pair, [a][b2][d]            33.5 MB
__device__ float g_Q [H*LL*DH];   // [h][i][n][c]                     67 MB
__device__ float g_K [H*LL*DH];   // [h][j][n][c]                     67 MB
__device__ float g_V [H*LL*DH];   // [h][j][k][d]                     67 MB
__device__ float g_G [LL*HD];     // gate, [i][k][m]                  67 MB
__device__ float g_Bp[H*LL];      // [h][i][j]                        2 MB
__device__ float g_A [H*LL];      // logits -> attn, [h][i][j]        2 MB
__device__ float g_O1[H*LL*DH];   // [h][i][k*32+d]                   67 MB

__device__ __forceinline__ float fixnum(float x){
    if (isnan(x)) return 0.f;
    if (isinf(x)) return x > 0.f ? 3.4028234663852886e38f : -3.4028234663852886e38f;
    return x;
}

// -------- kernel 1: nan_to_num + transpose + layernorm of pair --------------
// Pn[a][b2][:] = LN(pair[b2][a][:])
__global__ void ln_pair_kernel(const float* __restrict__ pair,
                               const float* __restrict__ g,
                               const float* __restrict__ b){
    int bid = blockIdx.x;           // a*L + b2
    int a  = bid >> 8, b2 = bid & 255;
    int d  = threadIdx.x;           // 128
    float x = fixnum(pair[(b2*L + a)*DP + d]);
    __shared__ float red[128];
    red[d] = x; __syncthreads();
    for (int s = 64; s > 0; s >>= 1){ if (d < s) red[d] += red[d+s]; __syncthreads(); }
    float m = red[0] * (1.f/DP);
    __syncthreads();
    float c = x - m;
    red[d] = c*c; __syncthreads();
    for (int s = 64; s > 0; s >>= 1){ if (d < s) red[d] += red[d+s]; __syncthreads(); }
    float v = red[0] * (1.f/DP);
    g_Pn[bid*DP + d] = c * rsqrtf(v + 1e-5f) * g[d] + b[d];
}

// -------- kernel 2: bias LN + projection to per-head bias ------------------
// Bp[h][i][j] = LN(bias[j][i][:]) @ Wb[:,h]
__global__ void bias_proj_kernel(const float* __restrict__ bias,
                                 const float* __restrict__ g,
                                 const float* __restrict__ bb,
                                 const float* __restrict__ Wb){
    int bid = blockIdx.x;           // i*L + j
    int i = bid >> 8, j = bid & 255;
    int e = threadIdx.x;            // 128
    float x = fixnum(bias[(j*L + i)*DB + e]);
    __shared__ float red[128];
    __shared__ float xn[128];
    red[e] = x; __syncthreads();
    for (int s = 64; s > 0; s >>= 1){ if (e < s) red[e] += red[e+s]; __syncthreads(); }
    float m = red[0] * (1.f/DB);
    __syncthreads();
    float c = x - m;
    red[e] = c*c; __syncthreads();
    for (int s = 64; s > 0; s >>= 1){ if (e < s) red[e] += red[e+s]; __syncthreads(); }
    float v = red[0] * (1.f/DB);
    xn[e] = c * rsqrtf(v + 1e-5f) * g[e] + bb[e];
    __syncthreads();
    // 8 dot products over 128 elems: thread e -> h=e&7, strided partials
    int h = e & 7;
    int es = e >> 3;                // 0..15
    float acc = 0.f;
    #pragma unroll
    for (int s = 0; s < 8; s++){
        int ee = es + s*16;
        acc += xn[ee] * Wb[ee*H + h];
    }
    red[e] = acc; __syncthreads();
    if (e < 8){
        float t = 0.f;
        #pragma unroll
        for (int s = 0; s < 16; s++) t += red[e + s*8];
        g_Bp[(e*L + i)*L + j] = t;
    }
}

// -------- kernel 3: projection GEMM  Pn[65536x128] @ W[128x256] x4 ----------
// scatters Q/K/V into [h][b2][a][c] layout, gate -> sigmoid -> g_G
#define PBM 64
#define PBN 64
#define PBK 16
__global__ void proj_kernel(const float* __restrict__ Wq, const float* __restrict__ Wk,
                            const float* __restrict__ Wv, const float* __restrict__ Wg,
                            const float* __restrict__ bg){
    __shared__ float As[PBK][PBM+1];
    __shared__ float Bs[PBK][PBN];
    int tid = threadIdx.x;              // 256
    int bn  = blockIdx.x;               // 16 col tiles over 1024
    int bm  = blockIdx.y;               // 1024 row tiles
    int n0  = bn * PBN;
    int which = n0 >> 8;                // 0:Q 1:K 2:V 3:G
    const float* W = (which==0) ? Wq : (which==1) ? Wk : (which==2) ? Wv : Wg;
    int nn0 = n0 & 255;
    int r0  = bm * PBM;
    int ty = tid >> 4, tx = tid & 15;
    float acc[4][4] = {};
    for (int k0 = 0; k0 < DP; k0 += PBK){
        {   // A tile 64 rows x 16 k, transposed into As[k][m]
            int rl = tid >> 2;
            int kq = tid & 3;
            float4 va = *(const float4*)&g_Pn[(r0+rl)*DP + k0 + kq*4];
            As[kq*4+0][rl] = va.x; As[kq*4+1][rl] = va.y;
            As[kq*4+2][rl] = va.z; As[kq*4+3][rl] = va.w;
        }
        {   // B tile 16 k x 64 n
            int kl = tid >> 4;
            int nq = tid & 15;
            float4 vb = *(const float4*)&W[(k0+kl)*HD + nn0 + nq*4];
            *(float4*)&Bs[kl][nq*4] = vb;
        }
        __syncthreads();
        #pragma unroll
        for (int kk = 0; kk < PBK; kk++){
            float a[4], b[4];
            #pragma unroll
            for (int u = 0; u < 4; u++) a[u] = As[kk][ty*4+u];
            #pragma unroll
            for (int v = 0; v < 4; v++) b[v] = Bs[kk][tx*4+v];
            #pragma unroll
            for (int u = 0; u < 4; u++)
                #pragma unroll
                for (int v = 0; v < 4; v++) acc[u][v] += a[u]*b[v];
        }
        __syncthreads();
    }
    const float SQ = 0.17677669529663687f;  // 1/sqrt(DH)
    const float SK = 0.0625f;               // 1/sqrt(L)
    #pragma unroll
    for (int u = 0; u < 4; u++){
        int r  = r0 + ty*4 + u;
        int a_ = r >> 8, b2 = r & 255;
        #pragma unroll
        for (int v = 0; v < 4; v++){
            int mm = nn0 + tx*4 + v;
            float y = acc[u][v];
            if (which == 3){
                g_G[r*HD + mm] = 1.f/(1.f + expf(-(y + bg[mm])));
            } else {
                int h = mm >> 5, c = mm & 31;
                int dst = ((h*L + b2)*L + a_)*DH + c;
                if      (which == 0) g_Q[dst] = y * SQ;
                else if (which == 1) g_K[dst] = y * SK;
                else                 g_V[dst] = y;
            }
        }
    }
}

// -------- kernel 4: QK^T logits per head (256x256, K=8192) + bias + mask ----
__global__ void qk_kernel(const int* __restrict__ mask){
    __shared__ float As[32][64+1];
    __shared__ float Bs[32][64+1];
    int h  = blockIdx.z;
    int i0 = blockIdx.y * 64, j0 = blockIdx.x * 64;
    int tid = threadIdx.x;
    int ty = tid >> 4, tx = tid & 15;
    const float* Qh = g_Q + (size_t)h * (LL*DH);
    const float* Kh = g_K + (size_t)h * (LL*DH);
    float acc[4][4] = {};
    for (int k0 = 0; k0 < LDH; k0 += 32){
        #pragma unroll
        for (int it = 0; it < 8; it++){
            int idx = tid + it*256;
            int il = idx >> 5, rl = idx & 31;
            As[rl][il] = Qh[(i0+il)*LDH + k0 + rl];
            Bs[rl][il] = Kh[(j0+il)*LDH + k0 + rl];
        }
        __syncthreads();
        #pragma unroll
        for (int kk = 0; kk < 32; kk++){
            float a[4], b[4];
            #pragma unroll
            for (int u = 0; u < 4; u++) a[u] = As[kk][ty*4+u];
            #pragma unroll
            for (int v = 0; v < 4; v++) b[v] = Bs[kk][tx*4+v];
            #pragma unroll
            for (int u = 0; u < 4; u++)
                #pragma unroll
                for (int v = 0; v < 4; v++) acc[u][v] += a[u]*b[v];
        }
        __syncthreads();
    }
    #pragma unroll
    for (int u = 0; u < 4; u++){
        int i = i0 + ty*4 + u;
        bool mi = (mask[i] == 0);
        #pragma unroll
        for (int v = 0; v < 4; v++){
            int j = j0 + tx*4 + v;
            float val = acc[u][v] + g_Bp[(h*L + i)*L + j];
            if (mi || (mask[j] == 0)) val = -1e9f;
            g_A[(h*L + i)*L + j] = val;
        }
    }
}

// -------- kernel 5: softmax over j ------------------------------------------
__global__ void softmax_kernel(){
    int row = blockIdx.x;      // h*L + i
    int j = threadIdx.x;       // 256
    float v = g_A[row*L + j];
    __shared__ float red[256];
    red[j] = v; __syncthreads();
    for (int s = 128; s > 0; s >>= 1){ if (j < s) red[j] = fmaxf(red[j], red[j+s]); __syncthreads(); }
    float mx = red[0];
    __syncthreads();
    float e = expf(v - mx);
    red[j] = e; __syncthreads();
    for (int s = 128; s > 0; s >>= 1){ if (j < s) red[j] += red[j+s]; __syncthreads(); }
    g_A[row*L + j] = e / red[0];
}

// -------- kernel 6: AV per head: A[256x256] @ V[256x8192] -------------------
__global__ void av_kernel(){
    __shared__ float As[32][64+1];   // [j][i]
    __shared__ float Bs[32][64+1];   // [j][n]
    int h  = blockIdx.z;
    int n0 = blockIdx.x * 64;
    int i0 = blockIdx.y * 64;
    int tid = threadIdx.x;
    int ty = tid >> 4, tx = tid & 15;
    const float* Ah = g_A + (size_t)h * LL;
    const float* Vh = g_V + (size_t)h * (LL*DH);
    float acc[4][4] = {};
    for (int j0 = 0; j0 < L; j0 += 32){
        #pragma unroll
        for (int it = 0; it < 8; it++){
            int idx = tid + it*256;
            int il = idx >> 5, jl = idx & 31;
            As[jl][il] = Ah[(i0+il)*L + j0 + jl];
        }
        #pragma unroll
        for (int it = 0; it < 8; it++){
            int idx = tid + it*256;
            int jl = idx >> 6, nl = idx & 63;
            Bs[jl][nl] = Vh[(j0+jl)*LDH + n0 + nl];
        }
        __syncthreads();
        #pragma unroll
        for (int kk = 0; kk < 32; kk++){
            float a[4], b[4];
            #pragma unroll
            for (int u = 0; u < 4; u++) a[u] = As[kk][ty*4+u];
            #pragma unroll
            for (int v = 0; v < 4; v++) b[v] = Bs[kk][tx*4+v];
            #pragma unroll
            for (int u = 0; u < 4; u++)
                #pragma unroll
                for (int v = 0; v < 4; v++) acc[u][v] += a[u]*b[v];
        }
        __syncthreads();
    }
    #pragma unroll
    for (int u = 0; u < 4; u++)
        #pragma unroll
        for (int v = 0; v < 4; v++)
            g_O1[(size_t)h*(LL*DH) + (size_t)(i0+ty*4+u)*LDH + n0 + tx*4 + v] = acc[u][v];
}

// -------- kernel 7: gate * out @ Wo + bo, transpose, output mask ------------
__global__ void final_kernel(const int* __restrict__ mask,
                             const float* __restrict__ Wo,
                             const float* __restrict__ bo,
                             float* __restrict__ out){
    int bid = blockIdx.x;             // i*L + k
    int i = bid >> 8, k = bid & 255;
    int d = threadIdx.x;              // 128
    float* dst = out + (k*L + i)*DP;  // transposed write
    if (mask[i] == 0 || mask[k] == 0){ dst[d] = 0.f; return; }
    __shared__ float xs[HD];
    for (int m = d; m < HD; m += DP){
        int h = m >> 5, dd = m & 31;
        float o = g_O1[(size_t)h*(LL*DH) + (size_t)i*LDH + k*DH + dd];
        xs[m] = o * g_G[(size_t)bid*HD + m];
    }
    __syncthreads();
    float acc = bo[d];
    #pragma unroll 8
    for (int m = 0; m < HD; m++) acc += xs[m] * Wo[m*DP + d];
    dst[d] = acc;
}

// ---------------------------------------------------------------------------
extern "C" void kernel_launch(void* const* d_in, const int* in_sizes, int n_in,
                              void* d_out, int out_size){
    const float* pair   = (const float*)d_in[0];
    const float* bias   = (const float*)d_in[1];
    const int*   mask   = (const int*)  d_in[2];
    const float* g_pair = (const float*)d_in[3];
    const float* b_pair = (const float*)d_in[4];
    const float* g_bias = (const float*)d_in[5];
    const float* b_bias = (const float*)d_in[6];
    const float* Wq     = (const float*)d_in[7];
    const float* Wk     = (const float*)d_in[8];
    const float* Wv     = (const float*)d_in[9];
    const float* Wb     = (const float*)d_in[10];
    const float* Wg     = (const float*)d_in[11];
    const float* bg     = (const float*)d_in[12];
    const float* Wo     = (const float*)d_in[13];
    const float* bo     = (const float*)d_in[14];
    float* out = (float*)d_out;

    ln_pair_kernel  <<<LL, 128>>>(pair, g_pair, b_pair);
    bias_proj_kernel<<<LL, 128>>>(bias, g_bias, b_bias, Wb);
    proj_kernel     <<<dim3(16, 1024), 256>>>(Wq, Wk, Wv, Wg, bg);
    qk_kernel       <<<dim3(4, 4, 8), 256>>>(mask);
    softmax_kernel  <<<H*L, 256>>>();
    av_kernel       <<<dim3(128, 4, 8), 256>>>();
    final_kernel    <<<LL, 128>>>(mask, Wo, bo, out);
}

// round 2
// speedup vs baseline: 2.1699x; 2.1699x over previous
#include <cuda_runtime.h>
#include <math.h>
#include <stdint.h>

#define L   256
#define DP  128
#define DB  128
#define H   8
#define DH  32
#define HD  256      // H*DH
#define LL  (L*L)    // 65536
#define LDH (L*DH)   // 8192
#define KSPLIT 8

// ---------------- scratch (device globals; no runtime alloc) ----------------
__device__ float g_Pn[LL*DP];        // LN'd pair, [a][b2][d]
__device__ float g_Q [H*LL*DH];      // [h][i][n][c]
__device__ float g_K [H*LL*DH];      // [h][j][n][c]
__device__ float g_V [H*LL*DH];      // [h][j][k][d]
__device__ float g_G [LL*HD];        // gate, [i][k][m]
__device__ float g_Bp[H*LL];         // [h][i][j]
__device__ float g_A [H*LL];         // attn, [h][i][j]
__device__ float g_Apart[KSPLIT*H*LL]; // split-K partials of logits
__device__ float g_O1[H*LL*DH];      // [h][i][k*32+d]

__device__ __forceinline__ float fixnum(float x){
    if (isnan(x)) return 0.f;
    if (isinf(x)) return x > 0.f ? 3.4028234663852886e38f : -3.4028234663852886e38f;
    return x;
}

__device__ __forceinline__ uint32_t f2t(float x){
    uint32_t u; asm("cvt.rna.tf32.f32 %0, %1;" : "=r"(u) : "f"(x)); return u;
}

__device__ __forceinline__ void mma_tf32(float c[4],
        uint32_t a0, uint32_t a1, uint32_t a2, uint32_t a3,
        uint32_t b0, uint32_t b1){
    asm volatile(
        "mma.sync.aligned.m16n8k8.row.col.f32.tf32.tf32.f32 "
        "{%0,%1,%2,%3},{%4,%5,%6,%7},{%8,%9},{%0,%1,%2,%3};"
        : "+f"(c[0]), "+f"(c[1]), "+f"(c[2]), "+f"(c[3])
        : "r"(a0), "r"(a1), "r"(a2), "r"(a3), "r"(b0), "r"(b1));
}

#define KPAD 36   // padded smem k-stride: (36*g + t) % 32 covers all banks

// -------- kernel 1: nan_to_num + transpose + layernorm of pair --------------
__global__ void ln_pair_kernel(const float* __restrict__ pair,
                               const float* __restrict__ g,
                               const float* __restrict__ b){
    int bid = blockIdx.x;           // a*L + b2
    int a  = bid >> 8, b2 = bid & 255;
    int d  = threadIdx.x;           // 128
    float x = fixnum(pair[(b2*L + a)*DP + d]);
    __shared__ float red[128];
    red[d] = x; __syncthreads();
    for (int s = 64; s > 0; s >>= 1){ if (d < s) red[d] += red[d+s]; __syncthreads(); }
    float m = red[0] * (1.f/DP);
    __syncthreads();
    float c = x - m;
    red[d] = c*c; __syncthreads();
    for (int s = 64; s > 0; s >>= 1){ if (d < s) red[d] += red[d+s]; __syncthreads(); }
    float v = red[0] * (1.f/DP);
    g_Pn[bid*DP + d] = c * rsqrtf(v + 1e-5f) * g[d] + b[d];
}

// -------- kernel 2: bias LN + projection to per-head bias -------------------
__global__ void bias_proj_kernel(const float* __restrict__ bias,
                                 const float* __restrict__ g,
                                 const float* __restrict__ bb,
                                 const float* __restrict__ Wb){
    int bid = blockIdx.x;           // i*L + j
    int i = bid >> 8, j = bid & 255;
    int e = threadIdx.x;            // 128
    float x = fixnum(bias[(j*L + i)*DB + e]);
    __shared__ float red[128];
    __shared__ float xn[128];
    red[e] = x; __syncthreads();
    for (int s = 64; s > 0; s >>= 1){ if (e < s) red[e] += red[e+s]; __syncthreads(); }
    float m = red[0] * (1.f/DB);
    __syncthreads();
    float c = x - m;
    red[e] = c*c; __syncthreads();
    for (int s = 64; s > 0; s >>= 1){ if (e < s) red[e] += red[e+s]; __syncthreads(); }
    float v = red[0] * (1.f/DB);
    xn[e] = c * rsqrtf(v + 1e-5f) * g[e] + bb[e];
    __syncthreads();
    int h = e & 7;
    int es = e >> 3;
    float acc = 0.f;
    #pragma unroll
    for (int s = 0; s < 8; s++){
        int ee = es + s*16;
        acc += xn[ee] * Wb[ee*H + h];
    }
    red[e] = acc; __syncthreads();
    if (e < 8){
        float t = 0.f;
        #pragma unroll
        for (int s = 0; s < 16; s++) t += red[e + s*8];
        g_Bp[(e*L + i)*L + j] = t;
    }
}

// -------- kernel 3: projection GEMM via tf32 MMA ----------------------------
// C[65536 x 1024] = Pn @ [Wq|Wk|Wv|Wg], scatter to Q/K/V layouts + gated sigmoid
__global__ __launch_bounds__(256) void proj_mma(
        const float* __restrict__ Wq, const float* __restrict__ Wk,
        const float* __restrict__ Wv, const float* __restrict__ Wg,
        const float* __restrict__ bg){
    __shared__ uint32_t As[128][KPAD];
    __shared__ uint32_t Bs[128][KPAD];
    int tid = threadIdx.x;
    int warp = tid >> 5, lane = tid & 31;
    int gid = lane >> 2, tig = lane & 3;
    int bn = blockIdx.x;                 // 0..7 col tiles of 128 over 1024
    int r0 = blockIdx.y * 128;
    int n0 = bn * 128;
    int which = n0 >> 8;                 // 0:Q 1:K 2:V 3:G
    const float* W = (which==0) ? Wq : (which==1) ? Wk : (which==2) ? Wv : Wg;
    int nn0 = n0 & 255;
    int wm = (warp >> 2) * 64, wn = (warp & 3) * 32;
    float c[4][4][4] = {};
    for (int k0 = 0; k0 < DP; k0 += 32){
        #pragma unroll
        for (int it = 0; it < 4; it++){
            int idx = tid + it*256; int row = idx >> 3, kq = idx & 7;
            float4 v = *(const float4*)&g_Pn[(size_t)(r0+row)*DP + k0 + kq*4];
            uint32_t* p = &As[row][kq*4];
            p[0]=f2t(v.x); p[1]=f2t(v.y); p[2]=f2t(v.z); p[3]=f2t(v.w);
        }
        #pragma unroll
        for (int it = 0; it < 4; it++){
            int idx = tid + it*256; int kl = idx >> 5, nq = idx & 31;
            float4 v = *(const float4*)&W[(size_t)(k0+kl)*HD + nn0 + nq*4];
            Bs[nq*4+0][kl]=f2t(v.x); Bs[nq*4+1][kl]=f2t(v.y);
            Bs[nq*4+2][kl]=f2t(v.z); Bs[nq*4+3][kl]=f2t(v.w);
        }
        __syncthreads();
        #pragma unroll
        for (int ks = 0; ks < 32; ks += 8){
            uint32_t a[4][4], b[4][2];
            #pragma unroll
            for (int mt = 0; mt < 4; mt++){
                int m = wm + mt*16;
                a[mt][0]=As[m+gid  ][ks+tig]; a[mt][1]=As[m+gid+8][ks+tig];
                a[mt][2]=As[m+gid  ][ks+tig+4]; a[mt][3]=As[m+gid+8][ks+tig+4];
            }
            #pragma unroll
            for (int nt = 0; nt < 4; nt++){
                int n = wn + nt*8;
                b[nt][0]=Bs[n+gid][ks+tig]; b[nt][1]=Bs[n+gid][ks+tig+4];
            }
            #pragma unroll
            for (int mt = 0; mt < 4; mt++)
                #pragma unroll
                for (int nt = 0; nt < 4; nt++)
                    mma_tf32(c[mt][nt], a[mt][0],a[mt][1],a[mt][2],a[mt][3],
                             b[nt][0], b[nt][1]);
        }
        __syncthreads();
    }
    const float SQ = 0.17677669529663687f;  // 1/sqrt(DH)
    const float SK = 0.0625f;               // 1/sqrt(L)
    #pragma unroll
    for (int mt = 0; mt < 4; mt++){
        #pragma unroll
        for (int nt = 0; nt < 4; nt++){
            #pragma unroll
            for (int half = 0; half < 2; half++){
                int row = r0 + wm + mt*16 + gid + half*8;
                int a_ = row >> 8, b2 = row & 255;
                int mm = nn0 + wn + nt*8 + 2*tig;
                float y0 = c[mt][nt][half*2+0];
                float y1 = c[mt][nt][half*2+1];
                if (which == 3){
                    y0 = 1.f/(1.f + expf(-(y0 + bg[mm])));
                    y1 = 1.f/(1.f + expf(-(y1 + bg[mm+1])));
                    *(float2*)&g_G[(size_t)row*HD + mm] = make_float2(y0, y1);
                } else {
                    int hh = mm >> 5, cc = mm & 31;
                    size_t dst = (((size_t)hh*L + b2)*L + a_)*DH + cc;
                    float s = (which==0) ? SQ : (which==1) ? SK : 1.f;
                    float2 val = make_float2(y0*s, y1*s);
                    if      (which==0) *(float2*)&g_Q[dst] = val;
                    else if (which==1) *(float2*)&g_K[dst] = val;
                    else               *(float2*)&g_V[dst] = val;
                }
            }
        }
    }
}

// -------- kernel 4: QK^T logits via tf32 MMA, split-K -----------------------
__global__ __launch_bounds__(256) void qk_mma(){
    __shared__ uint32_t As[128][KPAD];
    __shared__ uint32_t Bs[128][KPAD];
    int tid = threadIdx.x;
    int warp = tid >> 5, lane = tid & 31;
    int gid = lane >> 2, tig = lane & 3;
    int ks_id = blockIdx.x;              // 0..7 K slices of 1024
    int tile  = blockIdx.y;              // 0..3
    int i0 = (tile >> 1) * 128, j0 = (tile & 1) * 128;
    int h = blockIdx.z;
    const float* Qh = g_Q + (size_t)h * (LL*DH);
    const float* Kh = g_K + (size_t)h * (LL*DH);
    int wm = (warp >> 2) * 64, wn = (warp & 3) * 32;
    float c[4][4][4] = {};
    int kbeg = ks_id * 1024;
    for (int k0 = kbeg; k0 < kbeg + 1024; k0 += 32){
        #pragma unroll
        for (int it = 0; it < 4; it++){
            int idx = tid + it*256; int row = idx >> 3, kq = idx & 7;
            float4 v = *(const float4*)&Qh[(size_t)(i0+row)*LDH + k0 + kq*4];
            uint32_t* p = &As[row][kq*4];
            p[0]=f2t(v.x); p[1]=f2t(v.y); p[2]=f2t(v.z); p[3]=f2t(v.w);
            float4 w = *(const float4*)&Kh[(size_t)(j0+row)*LDH + k0 + kq*4];
            uint32_t* q = &Bs[row][kq*4];
            q[0]=f2t(w.x); q[1]=f2t(w.y); q[2]=f2t(w.z); q[3]=f2t(w.w);
        }
        __syncthreads();
        #pragma unroll
        for (int ks = 0; ks < 32; ks += 8){
            uint32_t a[4][4], b[4][2];
            #pragma unroll
            for (int mt = 0; mt < 4; mt++){
                int m = wm + mt*16;
                a[mt][0]=As[m+gid  ][ks+tig]; a[mt][1]=As[m+gid+8][ks+tig];
                a[mt][2]=As[m+gid  ][ks+tig+4]; a[mt][3]=As[m+gid+8][ks+tig+4];
            }
            #pragma unroll
            for (int nt = 0; nt < 4; nt++){
                int n = wn + nt*8;
                b[nt][0]=Bs[n+gid][ks+tig]; b[nt][1]=Bs[n+gid][ks+tig+4];
            }
            #pragma unroll
            for (int mt = 0; mt < 4; mt++)
                #pragma unroll
                for (int nt = 0; nt < 4; nt++)
                    mma_tf32(c[mt][nt], a[mt][0],a[mt][1],a[mt][2],a[mt][3],
                             b[nt][0], b[nt][1]);
        }
        __syncthreads();
    }
    float* dst = g_Apart + ((size_t)ks_id*H + h) * LL;
    #pragma unroll
    for (int mt = 0; mt < 4; mt++)
        #pragma unroll
        for (int nt = 0; nt < 4; nt++)
            #pragma unroll
            for (int half = 0; half < 2; half++){
                int i = i0 + wm + mt*16 + gid + half*8;
                int j = j0 + wn + nt*8 + 2*tig;
                *(float2*)&dst[(size_t)i*L + j] =
                    make_float2(c[mt][nt][half*2], c[mt][nt][half*2+1]);
            }
}

// -------- kernel 5: reduce split-K + bias + mask + softmax ------------------
__global__ void softmax_fused(const int* __restrict__ mask){
    int row = blockIdx.x;      // h*L + i
    int h = row >> 8, i = row & 255;
    int j = threadIdx.x;       // 256
    float v = 0.f;
    #pragma unroll
    for (int s = 0; s < KSPLIT; s++)
        v += g_Apart[(((size_t)s*H + h)*L + i)*L + j];
    v += g_Bp[(size_t)row*L + j];
    if (mask[i] == 0 || mask[j] == 0) v = -1e9f;
    __shared__ float red[256];
    red[j] = v; __syncthreads();
    for (int s = 128; s > 0; s >>= 1){ if (j < s) red[j] = fmaxf(red[j], red[j+s]); __syncthreads(); }
    float mx = red[0];
    __syncthreads();
    float e = expf(v - mx);
    red[j] = e; __syncthreads();
    for (int s = 128; s > 0; s >>= 1){ if (j < s) red[j] += red[j+s]; __syncthreads(); }
    g_A[(size_t)row*L + j] = e / red[0];
}

// -------- kernel 6: AV via tf32 MMA ------------------------------------------
// per head: O1[256 x 8192] = A[256 x 256] @ V[256 x 8192]
__global__ __launch_bounds__(256) void av_mma(){
    __shared__ uint32_t As[128][KPAD];
    __shared__ uint32_t Bs[128][KPAD];
    int tid = threadIdx.x;
    int warp = tid >> 5, lane = tid & 31;
    int gid = lane >> 2, tig = lane & 3;
    int n0 = blockIdx.x * 128;
    int i0 = blockIdx.y * 128;
    int h  = blockIdx.z;
    const float* Ah = g_A + (size_t)h * LL;
    const float* Vh = g_V + (size_t)h * (LL*DH);
    int wm = (warp >> 2) * 64, wn = (warp & 3) * 32;
    float c[4][4][4] = {};
    for (int k0 = 0; k0 < L; k0 += 32){
        #pragma unroll
        for (int it = 0; it < 4; it++){
            int idx = tid + it*256; int row = idx >> 3, kq = idx & 7;
            float4 v = *(const float4*)&Ah[(size_t)(i0+row)*L + k0 + kq*4];
            uint32_t* p = &As[row][kq*4];
            p[0]=f2t(v.x); p[1]=f2t(v.y); p[2]=f2t(v.z); p[3]=f2t(v.w);
        }
        #pragma unroll
        for (int it = 0; it < 4; it++){
            int idx = tid + it*256; int jl = idx >> 5, nq = idx & 31;
            float4 v = *(const float4*)&Vh[(size_t)(k0+jl)*LDH + n0 + nq*4];
            Bs[nq*4+0][jl]=f2t(v.x); Bs[nq*4+1][jl]=f2t(v.y);
            Bs[nq*4+2][jl]=f2t(v.z); Bs[nq*4+3][jl]=f2t(v.w);
        }
        __syncthreads();
        #pragma unroll
        for (int ks = 0; ks < 32; ks += 8){
            uint32_t a[4][4], b[4][2];
            #pragma unroll
            for (int mt = 0; mt < 4; mt++){
                int m = wm + mt*16;
                a[mt][0]=As[m+gid  ][ks+tig]; a[mt][1]=As[m+gid+8][ks+tig];
                a[mt][2]=As[m+gid  ][ks+tig+4]; a[mt][3]=As[m+gid+8][ks+tig+4];
            }
            #pragma unroll
            for (int nt = 0; nt < 4; nt++){
                int n = wn + nt*8;
                b[nt][0]=Bs[n+gid][ks+tig]; b[nt][1]=Bs[n+gid][ks+tig+4];
            }
            #pragma unroll
            for (int mt = 0; mt < 4; mt++)
                #pragma unroll
                for (int nt = 0; nt < 4; nt++)
                    mma_tf32(c[mt][nt], a[mt][0],a[mt][1],a[mt][2],a[mt][3],
                             b[nt][0], b[nt][1]);
        }
        __syncthreads();
    }
    float* Oh = g_O1 + (size_t)h * (LL*DH);
    #pragma unroll
    for (int mt = 0; mt < 4; mt++)
        #pragma unroll
        for (int nt = 0; nt < 4; nt++)
            #pragma unroll
            for (int half = 0; half < 2; half++){
                int i = i0 + wm + mt*16 + gid + half*8;
                int n = n0 + wn + nt*8 + 2*tig;
                *(float2*)&Oh[(size_t)i*LDH + n] =
                    make_float2(c[mt][nt][half*2], c[mt][nt][half*2+1]);
            }
}

// -------- kernel 7: (gate*out) @ Wo + bo via tf32 MMA, transpose + mask -----
__global__ __launch_bounds__(256) void final_mma(
        const int* __restrict__ mask, const float* __restrict__ Wo,
        const float* __restrict__ bo, float* __restrict__ out){
    __shared__ uint32_t As[128][KPAD];
    __shared__ uint32_t Bs[128][KPAD];
    int tid = threadIdx.x;
    int warp = tid >> 5, lane = tid & 31;
    int gid = lane >> 2, tig = lane & 3;
    int r0 = blockIdx.x * 128;           // rows r = i*256 + k
    int i  = r0 >> 8;
    int k0r = r0 & 255;
    int wm = (warp >> 2) * 64, wn = (warp & 3) * 32;
    float c[4][4][4] = {};
    for (int kc = 0; kc < 8; kc++){      // m chunks of 32, h = kc
        #pragma unroll
        for (int it = 0; it < 4; it++){
            int idx = tid + it*256; int row = idx >> 3, dq = idx & 7;
            size_t obase = (size_t)kc*(LL*DH) + (size_t)i*LDH + (size_t)(k0r+row)*DH + dq*4;
            float4 o = *(const float4*)&g_O1[obase];
            float4 g = *(const float4*)&g_G[(size_t)(r0+row)*HD + kc*32 + dq*4];
            uint32_t* p = &As[row][dq*4];
            p[0]=f2t(o.x*g.x); p[1]=f2t(o.y*g.y); p[2]=f2t(o.z*g.z); p[3]=f2t(o.w*g.w);
        }
        #pragma unroll
        for (int it = 0; it < 4; it++){
            int idx = tid + it*256; int ml = idx >> 5, dq = idx & 31;
            float4 v = *(const float4*)&Wo[(size_t)(kc*32+ml)*DP + dq*4];
            Bs[dq*4+0][ml]=f2t(v.x); Bs[dq*4+1][ml]=f2t(v.y);
            Bs[dq*4+2][ml]=f2t(v.z); Bs[dq*4+3][ml]=f2t(v.w);
        }
        __syncthreads();
        #pragma unroll
        for (int ks = 0; ks < 32; ks += 8){
            uint32_t a[4][4], b[4][2];
            #pragma unroll
            for (int mt = 0; mt < 4; mt++){
                int m = wm + mt*16;
                a[mt][0]=As[m+gid  ][ks+tig]; a[mt][1]=As[m+gid+8][ks+tig];
                a[mt][2]=As[m+gid  ][ks+tig+4]; a[mt][3]=As[m+gid+8][ks+tig+4];
            }
            #pragma unroll
            for (int nt = 0; nt < 4; nt++){
                int n = wn + nt*8;
                b[nt][0]=Bs[n+gid][ks+tig]; b[nt][1]=Bs[n+gid][ks+tig+4];
            }
            #pragma unroll
            for (int mt = 0; mt < 4; mt++)
                #pragma unroll
                for (int nt = 0; nt < 4; nt++)
                    mma_tf32(c[mt][nt], a[mt][0],a[mt][1],a[mt][2],a[mt][3],
                             b[nt][0], b[nt][1]);
        }
        __syncthreads();
    }
    bool mi = (mask[i] == 0);
    #pragma unroll
    for (int mt = 0; mt < 4; mt++)
        #pragma unroll
        for (int nt = 0; nt < 4; nt++)
            #pragma unroll
            for (int half = 0; half < 2; half++){
                int rowl = wm + mt*16 + gid + half*8;
                int k = k0r + rowl;
                int col = wn + nt*8 + 2*tig;
                float y0 = c[mt][nt][half*2+0] + bo[col];
                float y1 = c[mt][nt][half*2+1] + bo[col+1];
                if (mi || mask[k] == 0){ y0 = 0.f; y1 = 0.f; }
                *(float2*)&out[((size_t)k*L + i)*DP + col] = make_float2(y0, y1);
            }
}

// ---------------------------------------------------------------------------
extern "C" void kernel_launch(void* const* d_in, const int* in_sizes, int n_in,
                              void* d_out, int out_size){
    const float* pair   = (const float*)d_in[0];
    const float* bias   = (const float*)d_in[1];
    const int*   mask   = (const int*)  d_in[2];
    const float* g_pair = (const float*)d_in[3];
    const float* b_pair = (const float*)d_in[4];
    const float* g_bias = (const float*)d_in[5];
    const float* b_bias = (const float*)d_in[6];
    const float* Wq     = (const float*)d_in[7];
    const float* Wk     = (const float*)d_in[8];
    const float* Wv     = (const float*)d_in[9];
    const float* Wb     = (const float*)d_in[10];
    const float* Wg     = (const float*)d_in[11];
    const float* bg     = (const float*)d_in[12];
    const float* Wo     = (const float*)d_in[13];
    const float* bo     = (const float*)d_in[14];
    float* out = (float*)d_out;

    ln_pair_kernel  <<<LL, 128>>>(pair, g_pair, b_pair);
    bias_proj_kernel<<<LL, 128>>>(bias, g_bias, b_bias, Wb);
    proj_mma        <<<dim3(8, 512), 256>>>(Wq, Wk, Wv, Wg, bg);
    qk_mma          <<<dim3(KSPLIT, 4, H), 256>>>();
    softmax_fused   <<<H*L, 256>>>(mask);
    av_mma          <<<dim3(64, 2, H), 256>>>();
    final_mma       <<<512, 256>>>(mask, Wo, bo, out);
}

// round 3
// speedup vs baseline: 3.2635x; 1.5040x over previous
#include <cuda_runtime.h>
#include <math.h>
#include <stdint.h>

#define L   256
#define DP  128
#define DB  128
#define H   8
#define DH  32
#define HD  256      // H*DH
#define LL  (L*L)    // 65536
#define LDH (L*DH)   // 8192
#define KSPLIT 8

#define KPAD 36      // A smem k-stride (words): banks 4*gid+tig, conflict-free
#define BNP  132     // B(kn) smem n-stride (words): banks 4*tig+gid, conflict-free

// ---------------- scratch (device globals; no runtime alloc) ----------------
// All GEMM operands below are stored PRE-ROUNDED to tf32 (as float bits).
__device__ float g_Pn[LL*DP];          // LN'd pair (tf32)
__device__ float g_Q [H*LL*DH];        // (tf32)
__device__ float g_K [H*LL*DH];        // (tf32)
__device__ float g_V [H*LL*DH];        // (tf32)
__device__ float g_G [LL*HD];          // gate (fp32, used elementwise)
__device__ float g_Bp[H*LL];           // bias proj (fp32)
__device__ float g_A [H*LL];           // attn probs (tf32)
__device__ float g_Apart[KSPLIT*H*LL]; // split-K logit partials (fp32)
__device__ float g_O1[H*LL*DH];        // gated AV output (tf32)
__device__ float g_Wqt[DP*HD], g_Wkt[DP*HD], g_Wvt[DP*HD], g_Wgt[DP*HD];
__device__ float g_Wot[HD*DP];

__device__ __forceinline__ float fixnum(float x){
    if (isnan(x)) return 0.f;
    if (isinf(x)) return x > 0.f ? 3.4028234663852886e38f : -3.4028234663852886e38f;
    return x;
}
__device__ __forceinline__ uint32_t f2t(float x){
    uint32_t u; asm("cvt.rna.tf32.f32 %0, %1;" : "=r"(u) : "f"(x)); return u;
}
__device__ __forceinline__ float rt(float x){ return __uint_as_float(f2t(x)); }

__device__ __forceinline__ void mma_tf32(float c[4],
        uint32_t a0, uint32_t a1, uint32_t a2, uint32_t a3,
        uint32_t b0, uint32_t b1){
    asm volatile(
        "mma.sync.aligned.m16n8k8.row.col.f32.tf32.tf32.f32 "
        "{%0,%1,%2,%3},{%4,%5,%6,%7},{%8,%9},{%0,%1,%2,%3};"
        : "+f"(c[0]), "+f"(c[1]), "+f"(c[2]), "+f"(c[3])
        : "r"(a0), "r"(a1), "r"(a2), "r"(a3), "r"(b0), "r"(b1));
}
__device__ __forceinline__ void cpa16(uint32_t s_dst, const void* g_src){
    asm volatile("cp.async.cg.shared.global [%0], [%1], 16;" :: "r"(s_dst), "l"(g_src));
}
#define CP_COMMIT asm volatile("cp.async.commit_group;")
#define CP_WAIT1  asm volatile("cp.async.wait_group 1;")

// -------- kernel 0: convert weights to tf32 once per launch -----------------
__global__ void cvt_weights(const float* __restrict__ Wq, const float* __restrict__ Wk,
                            const float* __restrict__ Wv, const float* __restrict__ Wg,
                            const float* __restrict__ Wo){
    int i = blockIdx.x*256 + threadIdx.x;   // 32768 each
    g_Wqt[i] = rt(Wq[i]); g_Wkt[i] = rt(Wk[i]); g_Wvt[i] = rt(Wv[i]);
    g_Wgt[i] = rt(Wg[i]); g_Wot[i] = rt(Wo[i]);
}

// -------- kernel 1: nan_to_num + transpose + layernorm of pair --------------
__global__ void ln_pair_kernel(const float* __restrict__ pair,
                               const float* __restrict__ g,
                               const float* __restrict__ b){
    int bid = blockIdx.x;           // a*L + b2
    int a  = bid >> 8, b2 = bid & 255;
    int d  = threadIdx.x;           // 128
    float x = fixnum(pair[(b2*L + a)*DP + d]);
    __shared__ float ws[4];
    float s = x;
    #pragma unroll
    for (int o = 16; o > 0; o >>= 1) s += __shfl_xor_sync(0xffffffffu, s, o);
    if ((d & 31) == 0) ws[d >> 5] = s;
    __syncthreads();
    float m = (ws[0]+ws[1]+ws[2]+ws[3]) * (1.f/DP);
    float c = x - m;
    float q = c*c;
    #pragma unroll
    for (int o = 16; o > 0; o >>= 1) q += __shfl_xor_sync(0xffffffffu, q, o);
    __syncthreads();
    if ((d & 31) == 0) ws[d >> 5] = q;
    __syncthreads();
    float v = (ws[0]+ws[1]+ws[2]+ws[3]) * (1.f/DP);
    g_Pn[bid*DP + d] = rt(c * rsqrtf(v + 1e-5f) * g[d] + b[d]);
}

// -------- kernel 2: bias LN + projection to per-head bias -------------------
__global__ void bias_proj_kernel(const float* __restrict__ bias,
                                 const float* __restrict__ g,
                                 const float* __restrict__ bb,
                                 const float* __restrict__ Wb){
    int bid = blockIdx.x;           // i*L + j
    int i = bid >> 8, j = bid & 255;
    int e = threadIdx.x;            // 128
    float x = fixnum(bias[(j*L + i)*DB + e]);
    __shared__ float ws[4];
    __shared__ float xn[128];
    __shared__ float red[128];
    float s = x;
    #pragma unroll
    for (int o = 16; o > 0; o >>= 1) s += __shfl_xor_sync(0xffffffffu, s, o);
    if ((e & 31) == 0) ws[e >> 5] = s;
    __syncthreads();
    float m = (ws[0]+ws[1]+ws[2]+ws[3]) * (1.f/DB);
    float c = x - m;
    float q = c*c;
    #pragma unroll
    for (int o = 16; o > 0; o >>= 1) q += __shfl_xor_sync(0xffffffffu, q, o);
    __syncthreads();
    if ((e & 31) == 0) ws[e >> 5] = q;
    __syncthreads();
    float v = (ws[0]+ws[1]+ws[2]+ws[3]) * (1.f/DB);
    xn[e] = c * rsqrtf(v + 1e-5f) * g[e] + bb[e];
    __syncthreads();
    int h = e & 7;
    int es = e >> 3;
    float acc = 0.f;
    #pragma unroll
    for (int ss = 0; ss < 8; ss++){
        int ee = es + ss*16;
        acc += xn[ee] * Wb[ee*H + h];
    }
    red[e] = acc; __syncthreads();
    if (e < 8){
        float t = 0.f;
        #pragma unroll
        for (int ss = 0; ss < 16; ss++) t += red[e + ss*8];
        g_Bp[(e*L + i)*L + j] = t;
    }
}

// ================= pipelined tf32 MMA GEMMs =================================
// Warp tile 64x32, block 128x128, 3-stage cp.async pipeline.
// A smem: [3][128][KPAD] row-major-k ; B smem either row-k (qk) or kn layout.

#define SMEM_QK   (2*3*128*KPAD*4)
#define SMEM_KN   (3*128*KPAD*4 + 3*32*BNP*4)

// fragment compute over one 32-k stage, B in row-major [n][k] layout (slot of As2/Bs2)
#define COMPUTE_ROWB(AS, BS, slot)                                             \
    _Pragma("unroll")                                                          \
    for (int ks = 0; ks < 32; ks += 8){                                        \
        uint32_t a[4][4], b[4][2];                                             \
        _Pragma("unroll")                                                      \
        for (int mt = 0; mt < 4; mt++){                                        \
            int mrow = wm + mt*16;                                             \
            a[mt][0]=AS[slot][mrow+gid  ][ks+tig];                             \
            a[mt][1]=AS[slot][mrow+gid+8][ks+tig];                             \
            a[mt][2]=AS[slot][mrow+gid  ][ks+tig+4];                           \
            a[mt][3]=AS[slot][mrow+gid+8][ks+tig+4];                           \
        }                                                                      \
        _Pragma("unroll")                                                      \
        for (int nt = 0; nt < 4; nt++){                                        \
            int n = wn + nt*8;                                                 \
            b[nt][0]=BS[slot][n+gid][ks+tig];                                  \
            b[nt][1]=BS[slot][n+gid][ks+tig+4];                                \
        }                                                                      \
        _Pragma("unroll")                                                      \
        for (int mt = 0; mt < 4; mt++)                                         \
            _Pragma("unroll")                                                  \
            for (int nt = 0; nt < 4; nt++)                                     \
                mma_tf32(c[mt][nt], a[mt][0],a[mt][1],a[mt][2],a[mt][3],       \
                         b[nt][0], b[nt][1]);                                  \
    }

// B in [k][n] layout
#define COMPUTE_KNB(AS, BS, slot)                                              \
    _Pragma("unroll")                                                          \
    for (int ks = 0; ks < 32; ks += 8){                                        \
        uint32_t a[4][4], b[4][2];                                             \
        _Pragma("unroll")                                                      \
        for (int mt = 0; mt < 4; mt++){                                        \
            int mrow = wm + mt*16;                                             \
            a[mt][0]=AS[slot][mrow+gid  ][ks+tig];                             \
            a[mt][1]=AS[slot][mrow+gid+8][ks+tig];                             \
            a[mt][2]=AS[slot][mrow+gid  ][ks+tig+4];                           \
            a[mt][3]=AS[slot][mrow+gid+8][ks+tig+4];                           \
        }                                                                      \
        _Pragma("unroll")                                                      \
        for (int nt = 0; nt < 4; nt++){                                        \
            int n = wn + nt*8 + gid;                                           \
            b[nt][0]=BS[slot][ks+tig  ][n];                                    \
            b[nt][1]=BS[slot][ks+tig+4][n];                                    \
        }                                                                      \
        _Pragma("unroll")                                                      \
        for (int mt = 0; mt < 4; mt++)                                         \
            _Pragma("unroll")                                                  \
            for (int nt = 0; nt < 4; nt++)                                     \
                mma_tf32(c[mt][nt], a[mt][0],a[mt][1],a[mt][2],a[mt][3],       \
                         b[nt][0], b[nt][1]);                                  \
    }

// -------- kernel 3: projection GEMM ------------------------------------------
__global__ __launch_bounds__(256) void proj_mma(const float* __restrict__ bg){
    extern __shared__ uint32_t smem_u[];
    uint32_t (*As)[128][KPAD] = reinterpret_cast<uint32_t(*)[128][KPAD]>(smem_u);
    uint32_t (*Bs)[32][BNP]   = reinterpret_cast<uint32_t(*)[32][BNP]>(smem_u + 3*128*KPAD);
    uint32_t sbase = (uint32_t)__cvta_generic_to_shared(smem_u);
    uint32_t sA = sbase, sB = sbase + 3*128*KPAD*4;

    int tid = threadIdx.x;
    int warp = tid >> 5, lane = tid & 31;
    int gid = lane >> 2, tig = lane & 3;
    int bn = blockIdx.x;                 // 8 col tiles of 128 over 1024
    int r0 = blockIdx.y * 128;
    int n0 = bn * 128;
    int which = n0 >> 8;                 // 0:Q 1:K 2:V 3:G
    const float* W = (which==0) ? g_Wqt : (which==1) ? g_Wkt : (which==2) ? g_Wvt : g_Wgt;
    int nn0 = n0 & 255;
    int wm = (warp >> 2) * 64, wn = (warp & 3) * 32;
    float c[4][4][4] = {};

    auto load_stage = [&](int t, int slot){
        int k0 = t * 32;
        #pragma unroll
        for (int it = 0; it < 4; it++){
            int idx = tid + it*256;
            int row = idx >> 3, kq = idx & 7;
            cpa16(sA + (((slot*128 + row)*KPAD + kq*4) << 2),
                  &g_Pn[(size_t)(r0+row)*DP + k0 + kq*4]);
            int kl = idx >> 5, nq = idx & 31;
            cpa16(sB + (((slot*32 + kl)*BNP + nq*4) << 2),
                  &W[(size_t)(k0+kl)*HD + nn0 + nq*4]);
        }
    };
    const int NS = 4;
    load_stage(0,0); CP_COMMIT;
    load_stage(1,1); CP_COMMIT;
    for (int s = 0; s < NS; s++){
        CP_WAIT1; __syncthreads();
        int t = s + 2;
        if (t < NS) load_stage(t, t % 3);
        CP_COMMIT;
        int slot = s % 3;
        COMPUTE_KNB(As, Bs, slot);
    }

    const float SQ = 0.17677669529663687f;  // 1/sqrt(DH)
    const float SK = 0.0625f;               // 1/sqrt(L)
    #pragma unroll
    for (int mt = 0; mt < 4; mt++){
        #pragma unroll
        for (int nt = 0; nt < 4; nt++){
            #pragma unroll
            for (int half = 0; half < 2; half++){
                int row = r0 + wm + mt*16 + gid + half*8;
                int a_ = row >> 8, b2 = row & 255;
                int mm = nn0 + wn + nt*8 + 2*tig;
                float y0 = c[mt][nt][half*2+0];
                float y1 = c[mt][nt][half*2+1];
                if (which == 3){
                    y0 = 1.f/(1.f + expf(-(y0 + bg[mm])));
                    y1 = 1.f/(1.f + expf(-(y1 + bg[mm+1])));
                    *(float2*)&g_G[(size_t)row*HD + mm] = make_float2(y0, y1);
                } else {
                    int hh = mm >> 5, cc = mm & 31;
                    size_t dst = (((size_t)hh*L + b2)*L + a_)*DH + cc;
                    float sc = (which==0) ? SQ : (which==1) ? SK : 1.f;
                    float2 val = make_float2(rt(y0*sc), rt(y1*sc));
                    if      (which==0) *(float2*)&g_Q[dst] = val;
                    else if (which==1) *(float2*)&g_K[dst] = val;
                    else               *(float2*)&g_V[dst] = val;
                }
            }
        }
    }
}

// -------- kernel 4: QK^T logits, split-K -------------------------------------
__global__ __launch_bounds__(256) void qk_mma(){
    extern __shared__ uint32_t smem_u[];
    uint32_t (*As)[128][KPAD] = reinterpret_cast<uint32_t(*)[128][KPAD]>(smem_u);
    uint32_t (*Bs)[128][KPAD] = reinterpret_cast<uint32_t(*)[128][KPAD]>(smem_u + 3*128*KPAD);
    uint32_t sbase = (uint32_t)__cvta_generic_to_shared(smem_u);
    uint32_t sA = sbase, sB = sbase + 3*128*KPAD*4;

    int tid = threadIdx.x;
    int warp = tid >> 5, lane = tid & 31;
    int gid = lane >> 2, tig = lane & 3;
    int ks_id = blockIdx.x;
    int tile  = blockIdx.y;
    int i0 = (tile >> 1) * 128, j0 = (tile & 1) * 128;
    int h = blockIdx.z;
    const float* Qh = g_Q + (size_t)h * (LL*DH);
    const float* Kh = g_K + (size_t)h * (LL*DH);
    int wm = (warp >> 2) * 64, wn = (warp & 3) * 32;
    float c[4][4][4] = {};
    int kbeg = ks_id * 1024;

    auto load_stage = [&](int t, int slot){
        int k0 = kbeg + t * 32;
        #pragma unroll
        for (int it = 0; it < 4; it++){
            int idx = tid + it*256;
            int row = idx >> 3, kq = idx & 7;
            cpa16(sA + (((slot*128 + row)*KPAD + kq*4) << 2),
                  &Qh[(size_t)(i0+row)*LDH + k0 + kq*4]);
            cpa16(sB + (((slot*128 + row)*KPAD + kq*4) << 2),
                  &Kh[(size_t)(j0+row)*LDH + k0 + kq*4]);
        }
    };
    const int NS = 32;
    load_stage(0,0); CP_COMMIT;
    load_stage(1,1); CP_COMMIT;
    for (int s = 0; s < NS; s++){
        CP_WAIT1; __syncthreads();
        int t = s + 2;
        if (t < NS) load_stage(t, t % 3);
        CP_COMMIT;
        int slot = s % 3;
        COMPUTE_ROWB(As, Bs, slot);
    }

    float* dst = g_Apart + ((size_t)ks_id*H + h) * LL;
    #pragma unroll
    for (int mt = 0; mt < 4; mt++)
        #pragma unroll
        for (int nt = 0; nt < 4; nt++)
            #pragma unroll
            for (int half = 0; half < 2; half++){
                int i = i0 + wm + mt*16 + gid + half*8;
                int j = j0 + wn + nt*8 + 2*tig;
                *(float2*)&dst[(size_t)i*L + j] =
                    make_float2(c[mt][nt][half*2], c[mt][nt][half*2+1]);
            }
}

// -------- kernel 5: reduce split-K + bias + mask + softmax -------------------
__global__ void softmax_fused(const int* __restrict__ mask){
    int row = blockIdx.x;      // h*L + i
    int h = row >> 8, i = row & 255;
    int j = threadIdx.x;       // 256
    float v = 0.f;
    #pragma unroll
    for (int s = 0; s < KSPLIT; s++)
        v += g_Apart[(((size_t)s*H + h)*L + i)*L + j];
    v += g_Bp[(size_t)row*L + j];
    if (mask[i] == 0 || mask[j] == 0) v = -1e9f;
    __shared__ float red[256];
    red[j] = v; __syncthreads();
    for (int s = 128; s > 0; s >>= 1){ if (j < s) red[j] = fmaxf(red[j], red[j+s]); __syncthreads(); }
    float mx = red[0];
    __syncthreads();
    float e = expf(v - mx);
    red[j] = e; __syncthreads();
    for (int s = 128; s > 0; s >>= 1){ if (j < s) red[j] += red[j+s]; __syncthreads(); }
    g_A[(size_t)row*L + j] = rt(e / red[0]);
}

// -------- kernel 6: AV GEMM + gate fused in epilogue -------------------------
__global__ __launch_bounds__(256) void av_mma(){
    extern __shared__ uint32_t smem_u[];
    uint32_t (*As)[128][KPAD] = reinterpret_cast<uint32_t(*)[128][KPAD]>(smem_u);
    uint32_t (*Bs)[32][BNP]   = reinterpret_cast<uint32_t(*)[32][BNP]>(smem_u + 3*128*KPAD);
    uint32_t sbase = (uint32_t)__cvta_generic_to_shared(smem_u);
    uint32_t sA = sbase, sB = sbase + 3*128*KPAD*4;

    int tid = threadIdx.x;
    int warp = tid >> 5, lane = tid & 31;
    int gid = lane >> 2, tig = lane & 3;
    int n0 = blockIdx.x * 128;
    int i0 = blockIdx.y * 128;
    int h  = blockIdx.z;
    const float* Ah = g_A + (size_t)h * LL;
    const float* Vh = g_V + (size_t)h * (LL*DH);
    int wm = (warp >> 2) * 64, wn = (warp & 3) * 32;
    float c[4][4][4] = {};

    auto load_stage = [&](int t, int slot){
        int k0 = t * 32;
        #pragma unroll
        for (int it = 0; it < 4; it++){
            int idx = tid + it*256;
            int row = idx >> 3, kq = idx & 7;
            cpa16(sA + (((slot*128 + row)*KPAD + kq*4) << 2),
                  &Ah[(size_t)(i0+row)*L + k0 + kq*4]);
            int kl = idx >> 5, nq = idx & 31;
            cpa16(sB + (((slot*32 + kl)*BNP + nq*4) << 2),
                  &Vh[(size_t)(k0+kl)*LDH + n0 + nq*4]);
        }
    };
    const int NS = 8;
    load_stage(0,0); CP_COMMIT;
    load_stage(1,1); CP_COMMIT;
    for (int s = 0; s < NS; s++){
        CP_WAIT1; __syncthreads();
        int t = s + 2;
        if (t < NS) load_stage(t, t % 3);
        CP_COMMIT;
        int slot = s % 3;
        COMPUTE_KNB(As, Bs, slot);
    }

    float* Oh = g_O1 + (size_t)h * (LL*DH);
    #pragma unroll
    for (int mt = 0; mt < 4; mt++)
        #pragma unroll
        for (int nt = 0; nt < 4; nt++)
            #pragma unroll
            for (int half = 0; half < 2; half++){
                int i = i0 + wm + mt*16 + gid + half*8;
                int n = n0 + wn + nt*8 + 2*tig;
                // gate: G[(i*256 + k)*HD + h*32 + d], n = k*32 + d
                float2 gg = *(const float2*)&g_G[((size_t)i*L + (n>>5))*HD + h*DH + (n&31)];
                *(float2*)&Oh[(size_t)i*LDH + n] =
                    make_float2(rt(c[mt][nt][half*2]   * gg.x),
                                rt(c[mt][nt][half*2+1] * gg.y));
            }
}

// -------- kernel 7: (gated out) @ Wo + bo, transpose + mask ------------------
__global__ __launch_bounds__(256) void final_mma(
        const int* __restrict__ mask, const float* __restrict__ bo,
        float* __restrict__ out){
    extern __shared__ uint32_t smem_u[];
    uint32_t (*As)[128][KPAD] = reinterpret_cast<uint32_t(*)[128][KPAD]>(smem_u);
    uint32_t (*Bs)[32][BNP]   = reinterpret_cast<uint32_t(*)[32][BNP]>(smem_u + 3*128*KPAD);
    uint32_t sbase = (uint32_t)__cvta_generic_to_shared(smem_u);
    uint32_t sA = sbase, sB = sbase + 3*128*KPAD*4;

    int tid = threadIdx.x;
    int warp = tid >> 5, lane = tid & 31;
    int gid = lane >> 2, tig = lane & 3;
    int r0 = blockIdx.x * 128;           // rows r = i*256 + k
    int i  = r0 >> 8;
    int k0r = r0 & 255;
    int wm = (warp >> 2) * 64, wn = (warp & 3) * 32;
    float c[4][4][4] = {};

    auto load_stage = [&](int t, int slot){
        // stage t == head index; m = t*32 + (0..31)
        #pragma unroll
        for (int it = 0; it < 4; it++){
            int idx = tid + it*256;
            int row = idx >> 3, kq = idx & 7;
            cpa16(sA + (((slot*128 + row)*KPAD + kq*4) << 2),
                  &g_O1[(size_t)t*(LL*DH) + (size_t)i*LDH + (size_t)(k0r+row)*DH + kq*4]);
            int kl = idx >> 5, nq = idx & 31;
            cpa16(sB + (((slot*32 + kl)*BNP + nq*4) << 2),
                  &g_Wot[(size_t)(t*32+kl)*DP + nq*4]);
        }
    };
    const int NS = 8;
    load_stage(0,0); CP_COMMIT;
    load_stage(1,1); CP_COMMIT;
    for (int s = 0; s < NS; s++){
        CP_WAIT1; __syncthreads();
        int t = s + 2;
        if (t < NS) load_stage(t, t % 3);
        CP_COMMIT;
        int slot = s % 3;
        COMPUTE_KNB(As, Bs, slot);
    }

    bool mi = (mask[i] == 0);
    #pragma unroll
    for (int mt = 0; mt < 4; mt++)
        #pragma unroll
        for (int nt = 0; nt < 4; nt++)
            #pragma unroll
            for (int half = 0; half < 2; half++){
                int rowl = wm + mt*16 + gid + half*8;
                int k = k0r + rowl;
                int col = wn + nt*8 + 2*tig;
                float y0 = c[mt][nt][half*2+0] + bo[col];
                float y1 = c[mt][nt][half*2+1] + bo[col+1];
                if (mi || mask[k] == 0){ y0 = 0.f; y1 = 0.f; }
                *(float2*)&out[((size_t)k*L + i)*DP + col] = make_float2(y0, y1);
            }
}

// ---------------------------------------------------------------------------
extern "C" void kernel_launch(void* const* d_in, const int* in_sizes, int n_in,
                              void* d_out, int out_size){
    const float* pair   = (const float*)d_in[0];
    const float* bias   = (const float*)d_in[1];
    const int*   mask   = (const int*)  d_in[2];
    const float* g_pair = (const float*)d_in[3];
    const float* b_pair = (const float*)d_in[4];
    const float* g_bias = (const float*)d_in[5];
    const float* b_bias = (const float*)d_in[6];
    const float* Wq     = (const float*)d_in[7];
    const float* Wk     = (const float*)d_in[8];
    const float* Wv     = (const float*)d_in[9];
    const float* Wb     = (const float*)d_in[10];
    const float* Wg     = (const float*)d_in[11];
    const float* bg     = (const float*)d_in[12];
    const float* Wo     = (const float*)d_in[13];
    const float* bo     = (const float*)d_in[14];
    float* out = (float*)d_out;

    cudaFuncSetAttribute(proj_mma,  cudaFuncAttributeMaxDynamicSharedMemorySize, SMEM_KN);
    cudaFuncSetAttribute(qk_mma,    cudaFuncAttributeMaxDynamicSharedMemorySize, SMEM_QK);
    cudaFuncSetAttribute(av_mma,    cudaFuncAttributeMaxDynamicSharedMemorySize, SMEM_KN);
    cudaFuncSetAttribute(final_mma, cudaFuncAttributeMaxDynamicSharedMemorySize, SMEM_KN);

    cvt_weights     <<<128, 256>>>(Wq, Wk, Wv, Wg, Wo);
    ln_pair_kernel  <<<LL, 128>>>(pair, g_pair, b_pair);
    bias_proj_kernel<<<LL, 128>>>(bias, g_bias, b_bias, Wb);
    proj_mma        <<<dim3(8, 512), 256, SMEM_KN>>>(bg);
    qk_mma          <<<dim3(KSPLIT, 4, H), 256, SMEM_QK>>>();
    softmax_fused   <<<H*L, 256>>>(mask);
    av_mma          <<<dim3(64, 2, H), 256, SMEM_KN>>>();
    final_mma       <<<512, 256, SMEM_KN>>>(mask, bo, out);
}